// round 2
// baseline (speedup 1.0000x reference)
#include <cuda_runtime.h>
#include <math.h>

// Problem dimensions (fixed by the reference)
#define BATCH 8
#define SEQ   8192
#define DIM   512
#define HID   512
#define OUTD  512
#define MROWS (BATCH*SEQ)      // 65536
#define CHUNK 128
#define NCH   (SEQ/CHUNK)      // 64

// Scratch (device globals; no runtime allocation allowed)
static __device__ float g_lc[(size_t)MROWS*HID];       // log_coeffs  (B,S,H)
static __device__ float g_lv[(size_t)MROWS*HID];       // log_values  (B,S,H)
static __device__ float g_h [(size_t)MROWS*HID];       // hidden state h (B,S,H)
static __device__ float g_A  [(size_t)BATCH*NCH*HID];  // chunk sum of log_coeffs
static __device__ float g_LVc[(size_t)BATCH*NCH*HID];  // chunk log-value (zero-init state)
static __device__ float g_hin[(size_t)BATCH*NCH*HID];  // log h entering each chunk

// softplus(x) = max(x,0) + log1p(exp(-|x|))  (stable)
__device__ __forceinline__ float sp_f(float x) {
    return fmaxf(x, 0.0f) + log1pf(__expf(-fabsf(x)));
}
// logaddexp(a,b). Sentinel -1e30 behaves as -inf without NaNs:
// lae(-1e30, b)=b ; lae(-1e30,-1e30)= -1e30+log2 ~ -1e30.
__device__ __forceinline__ float lae(float a, float b) {
    float m = fmaxf(a, b);
    return m + log1pf(__expf(-fabsf(a - b)));
}

// ---------------------------------------------------------------------------
// GEMM1: hg = x(65536x512) @ W_hg(1024x512)^T, fused epilogue computing
// log_coeffs / log_values. Each block computes 128 rows x (64 hidden cols +
// their 64 matching gate cols), so hidden[m,n] and gate[m,n] land in the
// same thread for the fused nonlinearity.
// ---------------------------------------------------------------------------
__global__ __launch_bounds__(256) void gemm1_kernel(const float* __restrict__ x,
                                                    const float* __restrict__ Whg) {
    __shared__ float As[16][132];   // [k][m] transposed, padded
    __shared__ float Bs[16][132];   // [k][n] rows 0..63 = hidden, 64..127 = gate

    const int nb  = blockIdx.x * 64;     // hidden column base
    const int m0  = blockIdx.y * 128;    // row base
    const int tid = threadIdx.x;
    const int ty  = tid >> 4;            // 0..15
    const int tx  = tid & 15;            // 0..15
    const int lr  = tid >> 2;            // loader row 0..63
    const int lq  = (tid & 3) << 2;      // loader k offset {0,4,8,12}

    float acc[8][8];
#pragma unroll
    for (int i = 0; i < 8; i++)
#pragma unroll
        for (int j = 0; j < 8; j++) acc[i][j] = 0.0f;

    for (int k0 = 0; k0 < DIM; k0 += 16) {
#pragma unroll
        for (int hh = 0; hh < 2; hh++) {
            const int row = lr + hh * 64;
            float4 va = *(const float4*)(x + (size_t)(m0 + row) * DIM + k0 + lq);
            As[lq+0][row] = va.x; As[lq+1][row] = va.y;
            As[lq+2][row] = va.z; As[lq+3][row] = va.w;
            // B rows: r<64 -> W row nb+r (hidden); r>=64 -> W row 512+nb+(r-64) (gate)
            const int e = (row < 64) ? (nb + row) : (448 + nb + row);
            float4 vb = *(const float4*)(Whg + (size_t)e * DIM + k0 + lq);
            Bs[lq+0][row] = vb.x; Bs[lq+1][row] = vb.y;
            Bs[lq+2][row] = vb.z; Bs[lq+3][row] = vb.w;
        }
        __syncthreads();
#pragma unroll
        for (int k = 0; k < 16; k++) {
            float a[8], b[8];
            float4 t0 = *(const float4*)(&As[k][ty * 8]);
            float4 t1 = *(const float4*)(&As[k][ty * 8 + 4]);
            a[0]=t0.x; a[1]=t0.y; a[2]=t0.z; a[3]=t0.w;
            a[4]=t1.x; a[5]=t1.y; a[6]=t1.z; a[7]=t1.w;
            float4 u0 = *(const float4*)(&Bs[k][tx * 4]);        // hidden cols
            float4 u1 = *(const float4*)(&Bs[k][64 + tx * 4]);   // gate cols
            b[0]=u0.x; b[1]=u0.y; b[2]=u0.z; b[3]=u0.w;
            b[4]=u1.x; b[5]=u1.y; b[6]=u1.z; b[7]=u1.w;
#pragma unroll
            for (int i = 0; i < 8; i++)
#pragma unroll
                for (int j = 0; j < 8; j++)
                    acc[i][j] = fmaf(a[i], b[j], acc[i][j]);
        }
        __syncthreads();
    }

    // Fused epilogue: lc = -softplus(g); lv = -softplus(-g) + log_g(h)
#pragma unroll
    for (int i = 0; i < 8; i++) {
        const int m = m0 + ty * 8 + i;
        float lc4[4], lv4[4];
#pragma unroll
        for (int j = 0; j < 4; j++) {
            float hv = acc[i][j];
            float gv = acc[i][j + 4];
            float lgv = (hv >= 0.0f) ? __logf(hv + 0.5f) : -sp_f(-hv);
            lc4[j] = -sp_f(gv);
            lv4[j] = lgv - sp_f(-gv);
        }
        const size_t base = (size_t)m * HID + nb + tx * 4;
        *(float4*)(g_lc + base) = make_float4(lc4[0], lc4[1], lc4[2], lc4[3]);
        *(float4*)(g_lv + base) = make_float4(lv4[0], lv4[1], lv4[2], lv4[3]);
    }
}

// ---------------------------------------------------------------------------
// Chunked log-space scan: h_t = c_t*h_{t-1} + v_t (h_{-1}=0), in log domain
// log_h <- lae(lc + log_h, lv)
// ---------------------------------------------------------------------------
__global__ __launch_bounds__(512) void scan_pass1() {  // per-chunk summaries
    const int b = blockIdx.y, c = blockIdx.x, h = threadIdx.x;
    size_t base = ((size_t)(b * SEQ + c * CHUNK)) * HID + h;
    float A = 0.0f, LV = -1e30f;
    for (int t = 0; t < CHUNK; t++) {
        const float lc = g_lc[base];
        const float lv = g_lv[base];
        LV = lae(lc + LV, lv);
        A += lc;
        base += HID;
    }
    const size_t si = ((size_t)(b * NCH + c)) * HID + h;
    g_A[si]   = A;
    g_LVc[si] = LV;
}

__global__ __launch_bounds__(512) void scan_pass2() {  // inter-chunk scan
    const int b = blockIdx.x, h = threadIdx.x;
    float run = -1e30f;   // log h entering chunk 0 (state starts at 0)
    for (int c = 0; c < NCH; c++) {
        const size_t si = ((size_t)(b * NCH + c)) * HID + h;
        g_hin[si] = run;
        run = lae(g_A[si] + run, g_LVc[si]);
    }
}

__global__ __launch_bounds__(512) void scan_pass3(float* __restrict__ out_hn) {
    const int b = blockIdx.y, c = blockIdx.x, h = threadIdx.x;
    const size_t si = ((size_t)(b * NCH + c)) * HID + h;
    float lh = g_hin[si];
    size_t base = ((size_t)(b * SEQ + c * CHUNK)) * HID + h;
    for (int t = 0; t < CHUNK; t++) {
        lh = lae(g_lc[base] + lh, g_lv[base]);
        g_h[base] = __expf(lh);
        base += HID;
    }
    if (c == NCH - 1)
        out_hn[b * HID + h] = __expf(lh);   // h_n output
}

// ---------------------------------------------------------------------------
// GEMM2: out = h(65536x512) @ W_out(512x512)^T. Classic 128x128x16 SGEMM.
// ---------------------------------------------------------------------------
__global__ __launch_bounds__(256) void gemm2_kernel(const float* __restrict__ Wout,
                                                    float* __restrict__ out) {
    __shared__ float As[16][132];
    __shared__ float Bs[16][132];

    const int nb  = blockIdx.x * 128;
    const int m0  = blockIdx.y * 128;
    const int tid = threadIdx.x;
    const int ty  = tid >> 4;
    const int tx  = tid & 15;
    const int lr  = tid >> 2;
    const int lq  = (tid & 3) << 2;

    float acc[8][8];
#pragma unroll
    for (int i = 0; i < 8; i++)
#pragma unroll
        for (int j = 0; j < 8; j++) acc[i][j] = 0.0f;

    for (int k0 = 0; k0 < HID; k0 += 16) {
#pragma unroll
        for (int hh = 0; hh < 2; hh++) {
            const int row = lr + hh * 64;
            float4 va = *(const float4*)(g_h + (size_t)(m0 + row) * HID + k0 + lq);
            As[lq+0][row] = va.x; As[lq+1][row] = va.y;
            As[lq+2][row] = va.z; As[lq+3][row] = va.w;
            float4 vb = *(const float4*)(Wout + (size_t)(nb + row) * HID + k0 + lq);
            Bs[lq+0][row] = vb.x; Bs[lq+1][row] = vb.y;
            Bs[lq+2][row] = vb.z; Bs[lq+3][row] = vb.w;
        }
        __syncthreads();
#pragma unroll
        for (int k = 0; k < 16; k++) {
            float a[8], b[8];
            float4 t0 = *(const float4*)(&As[k][ty * 8]);
            float4 t1 = *(const float4*)(&As[k][ty * 8 + 4]);
            a[0]=t0.x; a[1]=t0.y; a[2]=t0.z; a[3]=t0.w;
            a[4]=t1.x; a[5]=t1.y; a[6]=t1.z; a[7]=t1.w;
            float4 u0 = *(const float4*)(&Bs[k][tx * 4]);
            float4 u1 = *(const float4*)(&Bs[k][64 + tx * 4]);
            b[0]=u0.x; b[1]=u0.y; b[2]=u0.z; b[3]=u0.w;
            b[4]=u1.x; b[5]=u1.y; b[6]=u1.z; b[7]=u1.w;
#pragma unroll
            for (int i = 0; i < 8; i++)
#pragma unroll
                for (int j = 0; j < 8; j++)
                    acc[i][j] = fmaf(a[i], b[j], acc[i][j]);
        }
        __syncthreads();
    }

#pragma unroll
    for (int i = 0; i < 8; i++) {
        const int m = m0 + ty * 8 + i;
        float* p0 = out + (size_t)m * OUTD + nb + tx * 4;
        float* p1 = out + (size_t)m * OUTD + nb + 64 + tx * 4;
        *(float4*)p0 = make_float4(acc[i][0], acc[i][1], acc[i][2], acc[i][3]);
        *(float4*)p1 = make_float4(acc[i][4], acc[i][5], acc[i][6], acc[i][7]);
    }
}

// ---------------------------------------------------------------------------
// Inputs (metadata order): x f32 (8,8192,512) | is_init bool(8) [unused by
// reference math] | W_hg f32 (1024,512) | W_out f32 (512,512)
// Output: out f32 (8,8192,512) followed by h_n f32 (8,1,512)
// ---------------------------------------------------------------------------
extern "C" void kernel_launch(void* const* d_in, const int* in_sizes, int n_in,
                              void* d_out, int out_size) {
    (void)in_sizes; (void)n_in; (void)out_size;
    const float* x    = (const float*)d_in[0];
    const float* Whg  = (const float*)d_in[2];
    const float* Wout = (const float*)d_in[3];
    float* out    = (float*)d_out;
    float* out_hn = out + (size_t)MROWS * OUTD;

    gemm1_kernel<<<dim3(HID / 64, MROWS / 128), 256>>>(x, Whg);
    scan_pass1 <<<dim3(NCH, BATCH), HID>>>();
    scan_pass2 <<<BATCH, HID>>>();
    scan_pass3 <<<dim3(NCH, BATCH), HID>>>(out_hn);
    gemm2_kernel<<<dim3(OUTD / 128, MROWS / 128), 256>>>(Wout, out);
}

// round 4
// speedup vs baseline: 1.6874x; 1.6874x over previous
#include <cuda_runtime.h>
#include <cuda_bf16.h>
#include <cstdint>
#include <math.h>

// Problem dimensions (fixed by the reference)
#define BATCH 8
#define SEQ   8192
#define DIM   512
#define HID   512
#define OUTD  512
#define MROWS (BATCH*SEQ)      // 65536
#define CHUNK 128
#define NCH   (SEQ/CHUNK)      // 64

// ---------------------------------------------------------------------------
// Device scratch (no runtime allocation allowed)
// ---------------------------------------------------------------------------
static __device__ float g_lc[(size_t)MROWS*HID];          // log_coeffs
static __device__ float g_lv[(size_t)MROWS*HID];          // log_values
static __device__ __nv_bfloat16 g_hhi[(size_t)MROWS*HID]; // h hi (bf16)
static __device__ __nv_bfloat16 g_hlo[(size_t)MROWS*HID]; // h lo (bf16)
static __device__ float g_A  [(size_t)BATCH*NCH*HID];
static __device__ float g_LVc[(size_t)BATCH*NCH*HID];
static __device__ float g_hin[(size_t)BATCH*NCH*HID];
static __device__ __nv_bfloat16 g_xhi[(size_t)MROWS*DIM];
static __device__ __nv_bfloat16 g_xlo[(size_t)MROWS*DIM];
static __device__ __nv_bfloat16 g_whi[(size_t)2*HID*DIM];
static __device__ __nv_bfloat16 g_wlo[(size_t)2*HID*DIM];
static __device__ __nv_bfloat16 g_ohi[(size_t)OUTD*HID];
static __device__ __nv_bfloat16 g_olo[(size_t)OUTD*HID];

// ---------------------------------------------------------------------------
// PTX helpers (sm_80+ only; no 'a'-suffix features)
// ---------------------------------------------------------------------------
__device__ __forceinline__ uint32_t smem_u32(const void* p) {
    uint32_t a;
    asm("{ .reg .u64 t; cvta.to.shared.u64 t, %1; cvt.u32.u64 %0, t; }" : "=r"(a) : "l"(p));
    return a;
}

#define CP_ASYNC16(dst, src) \
    asm volatile("cp.async.cg.shared.global [%0], [%1], 16;" :: "r"(dst), "l"(src))
#define CP_COMMIT() asm volatile("cp.async.commit_group;" ::: "memory")
#define CP_WAIT(N)  asm volatile("cp.async.wait_group %0;" :: "n"(N) : "memory")

#define LDMX4(r0, r1, r2, r3, a) \
    asm volatile("ldmatrix.sync.aligned.m8n8.x4.shared.b16 {%0,%1,%2,%3}, [%4];" \
        : "=r"(r0), "=r"(r1), "=r"(r2), "=r"(r3) : "r"(a))

#define MMA16816(c0, c1, c2, c3, a0, a1, a2, a3, b0, b1) \
    asm volatile("mma.sync.aligned.m16n8k16.row.col.f32.bf16.bf16.f32 " \
        "{%0,%1,%2,%3}, {%4,%5,%6,%7}, {%8,%9}, {%0,%1,%2,%3};" \
        : "+f"(c0), "+f"(c1), "+f"(c2), "+f"(c3) \
        : "r"(a0), "r"(a1), "r"(a2), "r"(a3), "r"(b0), "r"(b1))

// ---------------------------------------------------------------------------
// Math helpers
// ---------------------------------------------------------------------------
__device__ __forceinline__ float sp_f(float x) {
    return fmaxf(x, 0.0f) + log1pf(__expf(-fabsf(x)));
}
__device__ __forceinline__ float lae(float a, float b) {
    float m = fmaxf(a, b);
    return m + log1pf(__expf(-fabsf(a - b)));
}

// ---------------------------------------------------------------------------
// fp32 -> bf16 hi/lo split conversion
// ---------------------------------------------------------------------------
__global__ __launch_bounds__(256) void cvt_kernel(const float* __restrict__ src,
                                                  __nv_bfloat16* __restrict__ hi,
                                                  __nv_bfloat16* __restrict__ lo) {
    const size_t i = (size_t)blockIdx.x * blockDim.x + threadIdx.x;
    float4 v = ((const float4*)src)[i];
    __nv_bfloat16 hx = __float2bfloat16(v.x), hy = __float2bfloat16(v.y);
    __nv_bfloat16 hz = __float2bfloat16(v.z), hw = __float2bfloat16(v.w);
    __nv_bfloat16 lx = __float2bfloat16(v.x - __bfloat162float(hx));
    __nv_bfloat16 ly = __float2bfloat16(v.y - __bfloat162float(hy));
    __nv_bfloat16 lz = __float2bfloat16(v.z - __bfloat162float(hz));
    __nv_bfloat16 lw = __float2bfloat16(v.w - __bfloat162float(hw));
    ((__nv_bfloat162*)hi)[2*i]   = __nv_bfloat162(hx, hy);
    ((__nv_bfloat162*)hi)[2*i+1] = __nv_bfloat162(hz, hw);
    ((__nv_bfloat162*)lo)[2*i]   = __nv_bfloat162(lx, ly);
    ((__nv_bfloat162*)lo)[2*i+1] = __nv_bfloat162(lz, lw);
}

// ---------------------------------------------------------------------------
// mma.sync GEMM mainloop. Block 128Mx128N, K=512, kc=32, double-buffered
// cp.async. Split precision: acc += Ahi*Bhi + Ahi*Blo + Alo*Bhi (fp32 acc).
//
// SMEM stage layout (bytes from stage base), row stride 80B (40 bf16):
//   Ahi [0,10240)  Alo [10240,20480)  Bhi [20480,30720)  Blo [30720,40960)
// Stage = 40960B, 2 stages = 81920B (epilogue staging reuses this space).
//
// INTERLEAVE (GEMM1): B-tile n-row r maps to W_hg row (r even: nb + r/2
// hidden; r odd: 512 + nb + r/2 gate) so accumulator col pairs are
// (hidden, gate) of the same channel.
// ---------------------------------------------------------------------------
#define STG_B   40960
#define SMEM_BYTES (2*STG_B)

template<bool INTERLEAVE>
__device__ __forceinline__ void gemm_mainloop(const __nv_bfloat16* __restrict__ Ahi,
                                              const __nv_bfloat16* __restrict__ Alo,
                                              const __nv_bfloat16* __restrict__ Bhi,
                                              const __nv_bfloat16* __restrict__ Blo,
                                              int m0, int nb, uint32_t sbase,
                                              float acc[4][4][4]) {
    const int tid  = threadIdx.x;
    const int lane = tid & 31;
    const int wid  = tid >> 5;
    const int wm   = (wid >> 2) * 64;   // warp M offset (0/64)
    const int wn   = (wid & 3) * 32;    // warp N offset (0/32/64/96)

#pragma unroll
    for (int mi = 0; mi < 4; mi++)
#pragma unroll
        for (int ni = 0; ni < 4; ni++)
#pragma unroll
            for (int e = 0; e < 4; e++) acc[mi][ni][e] = 0.0f;

    // ---- stage loader: 8 cp.asyncs x 2 iters x 2 arrays per thread ----
    auto load_stage = [&](int j, int s) {
        const uint32_t st = sbase + s * STG_B;
        const int k0 = j * 32;
#pragma unroll
        for (int i = 0; i < 2; i++) {          // A chunks (512 per split)
            const int idx = tid + i * 256;
            const int r = idx >> 2, c = idx & 3;
            const size_t go = (size_t)(m0 + r) * 512 + k0 + c * 8;
            const uint32_t so = (uint32_t)(r * 80 + c * 16);
            CP_ASYNC16(st + so,         (const void*)(Ahi + go));
            CP_ASYNC16(st + 10240 + so, (const void*)(Alo + go));
        }
#pragma unroll
        for (int i = 0; i < 2; i++) {          // B chunks
            const int idx = tid + i * 256;
            const int r = idx >> 2, c = idx & 3;
            int wr;
            if (INTERLEAVE) wr = (r & 1) ? (512 + nb + (r >> 1)) : (nb + (r >> 1));
            else            wr = nb + r;
            const size_t go = (size_t)wr * 512 + k0 + c * 8;
            const uint32_t so = (uint32_t)(r * 80 + c * 16);
            CP_ASYNC16(st + 20480 + so, (const void*)(Bhi + go));
            CP_ASYNC16(st + 30720 + so, (const void*)(Blo + go));
        }
        CP_COMMIT();
    };

    load_stage(0, 0);

    for (int j = 0; j < 16; j++) {
        if (j + 1 < 16) load_stage(j + 1, (j + 1) & 1);
        if (j + 1 < 16) { CP_WAIT(1); } else { CP_WAIT(0); }
        __syncthreads();

        const uint32_t st = sbase + (j & 1) * STG_B;
#pragma unroll
        for (int s = 0; s < 2; s++) {          // two k16 steps per stage
            // ---- B fragments: 4 n-tiles, hi+lo ----
            uint32_t bh[4][2], bl[4][2];
#pragma unroll
            for (int p = 0; p < 2; p++) {
                const int nr = wn + p * 16 + (lane & 7) + ((lane & 16) ? 8 : 0);
                const int ko = s * 16 + ((lane & 8) ? 8 : 0);
                const uint32_t ba = st + 20480 + (uint32_t)(nr * 80 + ko * 2);
                LDMX4(bh[p*2][0], bh[p*2][1], bh[p*2+1][0], bh[p*2+1][1], ba);
                LDMX4(bl[p*2][0], bl[p*2][1], bl[p*2+1][0], bl[p*2+1][1], ba + 10240);
            }
            // ---- A fragments per m-tile + MMAs ----
#pragma unroll
            for (int mi = 0; mi < 4; mi++) {
                const int mr = wm + mi * 16 + (lane & 15);
                const int ko = s * 16 + ((lane & 16) ? 8 : 0);
                const uint32_t aa = st + (uint32_t)(mr * 80 + ko * 2);
                uint32_t ah[4], al[4];
                LDMX4(ah[0], ah[1], ah[2], ah[3], aa);
                LDMX4(al[0], al[1], al[2], al[3], aa + 10240);
#pragma unroll
                for (int ni = 0; ni < 4; ni++) {
                    MMA16816(acc[mi][ni][0], acc[mi][ni][1], acc[mi][ni][2], acc[mi][ni][3],
                             ah[0], ah[1], ah[2], ah[3], bh[ni][0], bh[ni][1]);
                    MMA16816(acc[mi][ni][0], acc[mi][ni][1], acc[mi][ni][2], acc[mi][ni][3],
                             ah[0], ah[1], ah[2], ah[3], bl[ni][0], bl[ni][1]);
                    MMA16816(acc[mi][ni][0], acc[mi][ni][1], acc[mi][ni][2], acc[mi][ni][3],
                             al[0], al[1], al[2], al[3], bh[ni][0], bh[ni][1]);
                }
            }
        }
        __syncthreads();
    }
}

// ---------------------------------------------------------------------------
// GEMM1: hg = x @ W_hg^T with fused lc/lv epilogue (interleaved channels).
// Grid: (HID/64, MROWS/128). Each block: 128 rows x 64 channels.
// ---------------------------------------------------------------------------
__global__ __launch_bounds__(256, 1)
void gemm1_mma() {
    extern __shared__ __align__(128) char smem[];
    const uint32_t sbase = smem_u32(smem);
    const int m0 = blockIdx.y * 128;
    const int nb = blockIdx.x * 64;

    float acc[4][4][4];
    gemm_mainloop<true>(g_xhi, g_xlo, g_whi, g_wlo, m0, nb, sbase, acc);

    // Epilogue: compute lc/lv in regs, stage via smem (stride 76 floats),
    // then coalesced float4 writes.
    float* lcs = (float*)smem;            // [128][76]
    float* lvs = lcs + 128 * 76;          // [128][76]
    const int tid = threadIdx.x, lane = tid & 31, wid = tid >> 5;
    const int wm = (wid >> 2) * 64;
    const int wn = (wid & 3) * 32;

#pragma unroll
    for (int mi = 0; mi < 4; mi++) {
#pragma unroll
        for (int ni = 0; ni < 4; ni++) {
            const int j  = (wn >> 1) + ni * 4 + (lane & 3);   // channel 0..63
            const int r0 = wm + mi * 16 + (lane >> 2);
#pragma unroll
            for (int e = 0; e < 2; e++) {
                const int r = r0 + e * 8;
                const float hv = acc[mi][ni][2*e];
                const float gv = acc[mi][ni][2*e + 1];
                const float lgv = (hv >= 0.0f) ? __logf(hv + 0.5f) : -sp_f(-hv);
                lcs[r * 76 + j] = -sp_f(gv);
                lvs[r * 76 + j] = lgv - sp_f(-gv);
            }
        }
    }
    __syncthreads();

    for (int idx = tid; idx < 2048; idx += 256) {
        const int r = idx >> 4, q = idx & 15;
        const size_t go = (size_t)(m0 + r) * HID + nb + q * 4;
        *(float4*)(g_lc + go) = *(float4*)&lcs[r * 76 + q * 4];
        *(float4*)(g_lv + go) = *(float4*)&lvs[r * 76 + q * 4];
    }
}

// ---------------------------------------------------------------------------
// GEMM2: out = h @ W_out^T. Grid: (OUTD/128, MROWS/128). Direct f32x2 stores.
// ---------------------------------------------------------------------------
__global__ __launch_bounds__(256, 1)
void gemm2_mma(float* __restrict__ out) {
    extern __shared__ __align__(128) char smem[];
    const uint32_t sbase = smem_u32(smem);
    const int m0 = blockIdx.y * 128;
    const int nb = blockIdx.x * 128;

    float acc[4][4][4];
    gemm_mainloop<false>(g_hhi, g_hlo, g_ohi, g_olo, m0, nb, sbase, acc);

    const int tid = threadIdx.x, lane = tid & 31, wid = tid >> 5;
    const int wm = (wid >> 2) * 64;
    const int wn = (wid & 3) * 32;

#pragma unroll
    for (int mi = 0; mi < 4; mi++) {
#pragma unroll
        for (int ni = 0; ni < 4; ni++) {
            const int col = nb + wn + ni * 8 + (lane & 3) * 2;
            const int r0  = m0 + wm + mi * 16 + (lane >> 2);
            *(float2*)(out + (size_t)r0 * OUTD + col)
                = make_float2(acc[mi][ni][0], acc[mi][ni][1]);
            *(float2*)(out + (size_t)(r0 + 8) * OUTD + col)
                = make_float2(acc[mi][ni][2], acc[mi][ni][3]);
        }
    }
}

// ---------------------------------------------------------------------------
// Chunked log-space scan (pass3 emits bf16 hi/lo h)
// ---------------------------------------------------------------------------
__global__ __launch_bounds__(512) void scan_pass1() {
    const int b = blockIdx.y, c = blockIdx.x, h = threadIdx.x;
    size_t base = ((size_t)(b * SEQ + c * CHUNK)) * HID + h;
    float A = 0.0f, LV = -1e30f;
    for (int t = 0; t < CHUNK; t++) {
        const float lc = g_lc[base];
        const float lv = g_lv[base];
        LV = lae(lc + LV, lv);
        A += lc;
        base += HID;
    }
    const size_t si = ((size_t)(b * NCH + c)) * HID + h;
    g_A[si]   = A;
    g_LVc[si] = LV;
}

__global__ __launch_bounds__(512) void scan_pass2() {
    const int b = blockIdx.x, h = threadIdx.x;
    float run = -1e30f;
    for (int c = 0; c < NCH; c++) {
        const size_t si = ((size_t)(b * NCH + c)) * HID + h;
        g_hin[si] = run;
        run = lae(g_A[si] + run, g_LVc[si]);
    }
}

__global__ __launch_bounds__(512) void scan_pass3(float* __restrict__ out_hn) {
    const int b = blockIdx.y, c = blockIdx.x, h = threadIdx.x;
    const size_t si = ((size_t)(b * NCH + c)) * HID + h;
    float lh = g_hin[si];
    size_t base = ((size_t)(b * SEQ + c * CHUNK)) * HID + h;
    float hv = 0.0f;
    for (int t = 0; t < CHUNK; t++) {
        lh = lae(g_lc[base] + lh, g_lv[base]);
        hv = __expf(lh);
        const __nv_bfloat16 hh = __float2bfloat16(hv);
        g_hhi[base] = hh;
        g_hlo[base] = __float2bfloat16(hv - __bfloat162float(hh));
        base += HID;
    }
    if (c == NCH - 1)
        out_hn[b * HID + h] = hv;
}

// ---------------------------------------------------------------------------
// Launch. Inputs: x f32 (8,8192,512) | is_init bool(8) | W_hg f32 (1024,512)
// | W_out f32 (512,512). Output: out f32 (B,S,O) ++ h_n f32 (B,1,H).
// ---------------------------------------------------------------------------
extern "C" void kernel_launch(void* const* d_in, const int* in_sizes, int n_in,
                              void* d_out, int out_size) {
    (void)in_sizes; (void)n_in; (void)out_size;
    const float* x    = (const float*)d_in[0];
    const float* Whg  = (const float*)d_in[2];
    const float* Wout = (const float*)d_in[3];
    float* out    = (float*)d_out;
    float* out_hn = out + (size_t)MROWS * OUTD;

    cudaFuncSetAttribute((const void*)gemm1_mma,
                         cudaFuncAttributeMaxDynamicSharedMemorySize, SMEM_BYTES);
    cudaFuncSetAttribute((const void*)gemm2_mma,
                         cudaFuncAttributeMaxDynamicSharedMemorySize, SMEM_BYTES);

    __nv_bfloat16 *xhi, *xlo, *whi, *wlo, *ohi, *olo;
    cudaGetSymbolAddress((void**)&xhi, g_xhi);
    cudaGetSymbolAddress((void**)&xlo, g_xlo);
    cudaGetSymbolAddress((void**)&whi, g_whi);
    cudaGetSymbolAddress((void**)&wlo, g_wlo);
    cudaGetSymbolAddress((void**)&ohi, g_ohi);
    cudaGetSymbolAddress((void**)&olo, g_olo);

    // bf16 hi/lo conversion prepass
    cvt_kernel<<<(MROWS * (size_t)DIM) / 4 / 256, 256>>>(x, xhi, xlo);
    cvt_kernel<<<(2 * HID * (size_t)DIM) / 4 / 256, 256>>>(Whg, whi, wlo);
    cvt_kernel<<<(OUTD * (size_t)HID) / 4 / 256, 256>>>(Wout, ohi, olo);

    // GEMM1 (mma.sync bf16 split) with fused lc/lv epilogue
    gemm1_mma<<<dim3(HID / 64, MROWS / 128), 256, SMEM_BYTES>>>();

    // scan
    scan_pass1<<<dim3(NCH, BATCH), HID>>>();
    scan_pass2<<<BATCH, HID>>>();
    scan_pass3<<<dim3(NCH, BATCH), HID>>>(out_hn);

    // GEMM2 (mma.sync bf16 split)
    gemm2_mma<<<dim3(OUTD / 128, MROWS / 128), 256, SMEM_BYTES>>>(out);
}